// round 16
// baseline (speedup 1.0000x reference)
#include <cuda_runtime.h>
#include <cuda_fp16.h>
#include <cstdint>

// ConditionalAffineCoupling — round 16: R12 epilogues with the R5 mainloop
// geometry (the best measured per-MAC config): BK=32, SW64, 4-stage pipeline,
// 256 threads, 2x4 warps of 64x32, 2 CTAs/SM. Single-term fp16 HMMA.

#define B_TOT 131072
#define DIM   512
#define CTXD  128
#define HID   2048
#define KIN   384

// ------------------------- device scratch (allocation-free) ----------------
__device__ __align__(1024) __half g_a1 [(size_t)B_TOT * KIN];
__device__ __align__(1024) __half g_h  [(size_t)B_TOT * HID];
__device__ __align__(1024) __half g_w1t[(size_t)HID * KIN];
__device__ __align__(1024) __half g_w2t[(size_t)DIM * HID];   // interleaved cols
__device__ __align__(1024) float  g_b2i[DIM];                 // interleaved bias
__device__ __align__(1024) float  g_ldp[4][B_TOT];            // log_det partials

// ------------------------- helpers -----------------------------------------
__device__ __forceinline__ uint32_t smem_u32(const void* p) {
    uint32_t a;
    asm("{ .reg .u64 t; cvta.to.shared.u64 t, %1; cvt.u32.u64 %0, t; }"
        : "=r"(a) : "l"(p));
    return a;
}
// SW64 swizzle for 64-byte rows (8-row atom), preserves 16B alignment.
__device__ __forceinline__ uint32_t swz64(uint32_t o) { return o ^ ((o >> 3) & 0x30); }

__device__ __forceinline__ void cp16(uint32_t sdst, const void* gsrc) {
    asm volatile("cp.async.cg.shared.global [%0], [%1], 16;"
                 :: "r"(sdst), "l"(gsrc));
}
__device__ __forceinline__ void ldsm4(uint32_t r[4], uint32_t addr) {
    asm volatile("ldmatrix.sync.aligned.m8n8.x4.shared.b16 {%0,%1,%2,%3}, [%4];"
                 : "=r"(r[0]), "=r"(r[1]), "=r"(r[2]), "=r"(r[3]) : "r"(addr));
}
__device__ __forceinline__ void mma16816(float c[4], const uint32_t a[4], const uint32_t b[2]) {
    asm volatile(
        "mma.sync.aligned.m16n8k16.row.col.f32.f16.f16.f32 "
        "{%0,%1,%2,%3}, {%4,%5,%6,%7}, {%8,%9}, {%0,%1,%2,%3};"
        : "+f"(c[0]), "+f"(c[1]), "+f"(c[2]), "+f"(c[3])
        : "r"(a[0]), "r"(a[1]), "r"(a[2]), "r"(a[3]), "r"(b[0]), "r"(b[1]));
}

// ------------------------- prep kernels ------------------------------------
__global__ void prep_w1t(const float* __restrict__ W1) {
    int i = blockIdx.x * 256 + threadIdx.x;
    if (i >= HID * KIN) return;
    int n = i / KIN, k = i % KIN;
    g_w1t[i] = __float2half(W1[(size_t)k * HID + n]);
}
// Interleave: new col 2j = old col j (s), new col 2j+1 = old col 256+j (t).
__global__ void prep_w2t(const float* __restrict__ W2, const float* __restrict__ b2) {
    int i = blockIdx.x * 256 + threadIdx.x;
    if (i < DIM) {
        int on = (i & 1) ? 256 + (i >> 1) : (i >> 1);
        g_b2i[i] = b2[on];
    }
    if (i >= DIM * HID) return;
    int n = i / HID, k = i % HID;
    int on = (n & 1) ? 256 + (n >> 1) : (n >> 1);
    g_w2t[i] = __float2half(W2[(size_t)k * DIM + on]);
}
__global__ void prep_a1(const float* __restrict__ x, const float* __restrict__ ctx) {
    size_t i = (size_t)blockIdx.x * 256 + threadIdx.x;
    if (i >= (size_t)B_TOT * KIN) return;
    int k = (int)(i % KIN);
    size_t row = i / KIN;
    float v = (k < 256) ? x[row * DIM + 2 * k] : ctx[row * CTXD + (k - 256)];
    g_a1[i] = __float2half(v);
}

// ------------------------- main GEMM (R5 geometry, single-term) -------------
// MODE 0: A=g_a1 (K=384),  B=g_w1t (2048xK); epi: relu(+b1) -> g_h fp16
// MODE 1: A=g_h  (K=2048), B=g_w2t (512xK, interleaved); epi: fused coupling
// CTA 128x128, BK=32 (64B rows, SW64), 4-stage cp.async (prologue 3,
// wait_group 2), 256 threads, 2x4 warps of 64x32. Stage: A 8K | B 8K = 16KB;
// x4 = 64KB. 2 CTAs/SM.
template <int MODE>
__global__ __launch_bounds__(256, 2)
void gemm_mma(const float* __restrict__ bias_in,
              const float* __restrict__ x,
              float* __restrict__ out)
{
    constexpr int KTOT   = MODE ? HID : KIN;
    constexpr int C      = KTOT / 32;
    constexpr int PITCH  = KTOT * 2;        // bytes per row (A and B^T K-major)
    constexpr int STAGE  = 16384;
    constexpr int B_OFF  = 8192;

    const float* bias = MODE ? (const float*)g_b2i : bias_in;

    extern __shared__ char smem[];
    const uint32_t sb = smem_u32(smem);
    const int tid  = threadIdx.x, lane = tid & 31, wid = tid >> 5;
    const int wm   = wid >> 2;              // 0..1  (64-row slabs)
    const int wn   = wid & 3;               // 0..3  (32-col slabs)
    const int n0   = blockIdx.x * 128;
    const int bm0  = blockIdx.y * 128;

    const char* A = (const char*)(MODE ? g_h   : g_a1)  + (size_t)bm0 * PITCH;
    const char* B = (const char*)(MODE ? g_w2t : g_w1t) + (size_t)n0  * PITCH;

    // loader: each region 128 rows x 4 chunks(16B) = 512 cp16; 2/thread/region
    const int r0c = tid >> 2, j0c = (tid & 3) * 16;
    const int r1c = (tid + 256) >> 2;

    auto load_stage = [&](int s) {
        const uint32_t base = sb + (s & 3) * STAGE;
        const size_t kb = (size_t)s * 64;
        uint32_t so0 = swz64((uint32_t)(r0c * 64 + j0c));
        uint32_t so1 = swz64((uint32_t)(r1c * 64 + j0c));
        size_t go0 = (size_t)r0c * PITCH + kb + j0c;
        size_t go1 = (size_t)r1c * PITCH + kb + j0c;
        cp16(base + so0,         A + go0);
        cp16(base + so1,         A + go1);
        cp16(base + B_OFF + so0, B + go0);
        cp16(base + B_OFF + so1, B + go1);
    };

    // ldmatrix lane address components (64B rows)
    const int a_row  = wm * 64 + (lane & 15);          // + mt*16
    const int a_byte = (lane >> 4) * 16;               // + ks*32
    const int b_l8   = lane & 7;
    const int b_grp  = lane >> 3;                      // 0..3
    const int b_row0 = wn * 32 + (b_grp >> 1) * 8 + b_l8;   // + p*16
    const int b_byte = (b_grp & 1) * 16;                    // + ks*32

    float acc[4][4][4] = {};

    load_stage(0); asm volatile("cp.async.commit_group;" ::: "memory");
    load_stage(1); asm volatile("cp.async.commit_group;" ::: "memory");
    load_stage(2); asm volatile("cp.async.commit_group;" ::: "memory");

    #pragma unroll 1
    for (int c = 0; c < C; ++c) {
        if (c < C - 3) asm volatile("cp.async.wait_group 2;" ::: "memory");
        else           asm volatile("cp.async.wait_group 0;" ::: "memory");
        __syncthreads();

        if (c + 3 < C) {
            load_stage(c + 3);
            asm volatile("cp.async.commit_group;" ::: "memory");
        }

        const uint32_t stb = sb + (c & 3) * STAGE;
        #pragma unroll
        for (int ks = 0; ks < 2; ++ks) {
            // B fragments: 2x ldsm4 cover all 4 n-tiles for this k16
            uint32_t bf[4][2];
            #pragma unroll
            for (int p = 0; p < 2; ++p) {
                uint32_t r4[4];
                ldsm4(r4, stb + B_OFF +
                    swz64((uint32_t)((b_row0 + p * 16) * 64 + ks * 32 + b_byte)));
                bf[2 * p][0] = r4[0]; bf[2 * p][1] = r4[1];
                bf[2 * p + 1][0] = r4[2]; bf[2 * p + 1][1] = r4[3];
            }
            #pragma unroll
            for (int mt = 0; mt < 4; ++mt) {
                uint32_t af[4];
                ldsm4(af, stb +
                    swz64((uint32_t)((a_row + mt * 16) * 64 + ks * 32 + a_byte)));
                #pragma unroll
                for (int nt = 0; nt < 4; ++nt) mma16816(acc[mt][nt], af, bf[nt]);
            }
        }
    }

    // ------------------------- epilogue -------------------------------------
    const int q = lane >> 2;                         // row-in-8
    const int npair = (lane & 3) * 2;

    if constexpr (MODE == 0) {
        #pragma unroll
        for (int nt = 0; nt < 4; ++nt) {
            const int gn = n0 + wn * 32 + nt * 8 + npair;
            const float bv0 = __ldg(bias + gn), bv1 = __ldg(bias + gn + 1);
            #pragma unroll
            for (int mt = 0; mt < 4; ++mt) {
                const int r0 = bm0 + wm * 64 + mt * 16 + q;
                __half2 v0 = __floats2half2_rn(fmaxf(acc[mt][nt][0] + bv0, 0.f),
                                               fmaxf(acc[mt][nt][1] + bv1, 0.f));
                __half2 v1 = __floats2half2_rn(fmaxf(acc[mt][nt][2] + bv0, 0.f),
                                               fmaxf(acc[mt][nt][3] + bv1, 0.f));
                *(__half2*)(g_h + (size_t)r0 * HID + gn)       = v0;
                *(__half2*)(g_h + (size_t)(r0 + 8) * HID + gn) = v1;
            }
        }
    } else {
        // Fused coupling: acc pair (c0,c1) = (s_raw, t_raw) for column pair gn.
        float ldp[8] = {0.f, 0.f, 0.f, 0.f, 0.f, 0.f, 0.f, 0.f};
        #pragma unroll
        for (int nt = 0; nt < 4; ++nt) {
            const int gn = n0 + wn * 32 + nt * 8 + npair;
            const float bs = __ldg(bias + gn), bt = __ldg(bias + gn + 1);
            #pragma unroll
            for (int mt = 0; mt < 4; ++mt) {
                const int r0 = bm0 + wm * 64 + mt * 16 + q;
                #pragma unroll
                for (int hh = 0; hh < 2; ++hh) {
                    const int r = r0 + hh * 8;
                    float s_raw = acc[mt][nt][2 * hh]     + bs;
                    float t_val = acc[mt][nt][2 * hh + 1] + bt;
                    float e2 = __expf(2.f * s_raw);
                    float s  = 5.f * (1.f - 2.f / (e2 + 1.f));   // 5*tanh
                    ldp[mt * 2 + hh] += s;
                    float2 xv = *(const float2*)(x + (size_t)r * DIM + gn);
                    float2 o  = make_float2(xv.x, xv.y * __expf(s) + t_val);
                    *(float2*)(out + (size_t)r * DIM + gn) = o;
                }
            }
        }
        // quad reduce (lanes of a quad share the same rows)
        #pragma unroll
        for (int i = 0; i < 8; ++i) {
            ldp[i] += __shfl_xor_sync(0xffffffffu, ldp[i], 1);
            ldp[i] += __shfl_xor_sync(0xffffffffu, ldp[i], 2);
        }
        __syncthreads();                     // smem (stages) now reusable
        float* red = (float*)smem;           // [128 rows][4 wn]
        if ((lane & 3) == 0) {
            #pragma unroll
            for (int i = 0; i < 8; ++i) {
                int row_local = wm * 64 + (i >> 1) * 16 + q + (i & 1) * 8;
                red[row_local * 4 + wn] = ldp[i];
            }
        }
        __syncthreads();
        if (tid < 128) {
            float p = red[tid * 4] + red[tid * 4 + 1] +
                      red[tid * 4 + 2] + red[tid * 4 + 3];
            g_ldp[blockIdx.x][bm0 + tid] = p;
        }
    }
}

// ------------------------- log_det final reduce -----------------------------
__global__ __launch_bounds__(256)
void ldred(float* __restrict__ out)
{
    int r = blockIdx.x * 256 + threadIdx.x;
    out[(size_t)B_TOT * DIM + r] =
        g_ldp[0][r] + g_ldp[1][r] + g_ldp[2][r] + g_ldp[3][r];
}

// ------------------------- launch ------------------------------------------
extern "C" void kernel_launch(void* const* d_in, const int* in_sizes, int n_in,
                              void* d_out, int out_size)
{
    const float* x   = (const float*)d_in[0];
    const float* ctx = (const float*)d_in[1];
    const float* W1  = (const float*)d_in[2];
    const float* b1  = (const float*)d_in[3];
    const float* W2  = (const float*)d_in[4];
    const float* b2  = (const float*)d_in[5];
    float* out = (float*)d_out;

    cudaFuncSetAttribute(gemm_mma<0>, cudaFuncAttributeMaxDynamicSharedMemorySize, 65536);
    cudaFuncSetAttribute(gemm_mma<1>, cudaFuncAttributeMaxDynamicSharedMemorySize, 65536);

    prep_w1t<<<(HID * KIN + 255) / 256, 256>>>(W1);
    prep_w2t<<<(DIM * HID + 255) / 256, 256>>>(W2, b2);
    prep_a1<<<(int)(((size_t)B_TOT * KIN + 255) / 256), 256>>>(x, ctx);

    gemm_mma<0><<<dim3(HID / 128, B_TOT / 128), 256, 65536>>>(b1, nullptr, nullptr);
    gemm_mma<1><<<dim3(DIM / 128, B_TOT / 128), 256, 65536>>>(nullptr, x, out);

    ldred<<<B_TOT / 256, 256>>>(out);
}

// round 17
// speedup vs baseline: 1.1245x; 1.1245x over previous
#include <cuda_runtime.h>
#include <cuda_fp16.h>
#include <cstdint>

// ConditionalAffineCoupling — round 17: 64x128 CTAs (128 threads, 4 warps of
// 64x32), 3 CTAs/SM — three independent barrier domains per SM to fill
// tensor-pipe bubbles. Per-warp mainloop identical to the proven R8 shape.
// Fused coupling epilogue in GEMM2; deterministic log_det partials.

#define B_TOT 131072
#define DIM   512
#define CTXD  128
#define HID   2048
#define KIN   384

// ------------------------- device scratch (allocation-free) ----------------
__device__ __align__(1024) __half g_a1 [(size_t)B_TOT * KIN];
__device__ __align__(1024) __half g_h  [(size_t)B_TOT * HID];
__device__ __align__(1024) __half g_w1t[(size_t)HID * KIN];
__device__ __align__(1024) __half g_w2t[(size_t)DIM * HID];   // interleaved cols
__device__ __align__(1024) float  g_b2i[DIM];                 // interleaved bias
__device__ __align__(1024) float  g_ldp[4][B_TOT];            // log_det partials

// ------------------------- helpers -----------------------------------------
__device__ __forceinline__ uint32_t smem_u32(const void* p) {
    uint32_t a;
    asm("{ .reg .u64 t; cvta.to.shared.u64 t, %1; cvt.u32.u64 %0, t; }"
        : "=r"(a) : "l"(p));
    return a;
}
__device__ __forceinline__ uint32_t swz128(uint32_t o) { return o ^ ((o >> 3) & 0x70); }

__device__ __forceinline__ void cp16(uint32_t sdst, const void* gsrc) {
    asm volatile("cp.async.cg.shared.global [%0], [%1], 16;"
                 :: "r"(sdst), "l"(gsrc));
}
__device__ __forceinline__ void ldsm4(uint32_t r[4], uint32_t addr) {
    asm volatile("ldmatrix.sync.aligned.m8n8.x4.shared.b16 {%0,%1,%2,%3}, [%4];"
                 : "=r"(r[0]), "=r"(r[1]), "=r"(r[2]), "=r"(r[3]) : "r"(addr));
}
__device__ __forceinline__ void mma16816(float c[4], const uint32_t a[4], const uint32_t b[2]) {
    asm volatile(
        "mma.sync.aligned.m16n8k16.row.col.f32.f16.f16.f32 "
        "{%0,%1,%2,%3}, {%4,%5,%6,%7}, {%8,%9}, {%0,%1,%2,%3};"
        : "+f"(c[0]), "+f"(c[1]), "+f"(c[2]), "+f"(c[3])
        : "r"(a[0]), "r"(a[1]), "r"(a[2]), "r"(a[3]), "r"(b[0]), "r"(b[1]));
}

// ------------------------- prep kernels ------------------------------------
__global__ void prep_w1t(const float* __restrict__ W1) {
    int i = blockIdx.x * 256 + threadIdx.x;
    if (i >= HID * KIN) return;
    int n = i / KIN, k = i % KIN;
    g_w1t[i] = __float2half(W1[(size_t)k * HID + n]);
}
// Interleave: new col 2j = old col j (s), new col 2j+1 = old col 256+j (t).
__global__ void prep_w2t(const float* __restrict__ W2, const float* __restrict__ b2) {
    int i = blockIdx.x * 256 + threadIdx.x;
    if (i < DIM) {
        int on = (i & 1) ? 256 + (i >> 1) : (i >> 1);
        g_b2i[i] = b2[on];
    }
    if (i >= DIM * HID) return;
    int n = i / HID, k = i % HID;
    int on = (n & 1) ? 256 + (n >> 1) : (n >> 1);
    g_w2t[i] = __float2half(W2[(size_t)k * DIM + on]);
}
__global__ void prep_a1(const float* __restrict__ x, const float* __restrict__ ctx) {
    size_t i = (size_t)blockIdx.x * 256 + threadIdx.x;
    if (i >= (size_t)B_TOT * KIN) return;
    int k = (int)(i % KIN);
    size_t row = i / KIN;
    float v = (k < 256) ? x[row * DIM + 2 * k] : ctx[row * CTXD + (k - 256)];
    g_a1[i] = __float2half(v);
}

// ------------------------- main GEMM (64x128 CTA, 4 warps) ------------------
// MODE 0: A=g_a1 (K=384),  B=g_w1t (2048xK); epi: relu(+b1) -> g_h fp16
// MODE 1: A=g_h  (K=2048), B=g_w2t (512xK, interleaved); epi: fused coupling
// CTA 64x128 (M x N), BK=64 (128B rows, SW128), 3-stage cp.async, 128 thr.
// 4 warps (wn 0..3), each 64 rows x 32 cols. Stage: A 8K | B 16K = 24KB;
// x3 stages = 72KB -> 3 CTAs/SM (216KB smem, 384 thr, ~110 regs).
template <int MODE>
__global__ __launch_bounds__(128, 3)
void gemm_mma(const float* __restrict__ bias_in,
              const float* __restrict__ x,
              float* __restrict__ out)
{
    constexpr int KTOT   = MODE ? HID : KIN;
    constexpr int C      = KTOT / 64;
    constexpr int PITCH  = KTOT * 2;        // bytes per row (A and B^T K-major)
    constexpr int STAGE  = 24576;
    constexpr int B_OFF  = 8192;

    const float* bias = MODE ? (const float*)g_b2i : bias_in;

    extern __shared__ char smem[];
    const uint32_t sb = smem_u32(smem);
    const int tid  = threadIdx.x, lane = tid & 31, wid = tid >> 5;
    const int wn   = wid;                   // 0..3  (32-col slabs)
    const int n0   = blockIdx.x * 128;
    const int bm0  = blockIdx.y * 64;

    const char* A = (const char*)(MODE ? g_h   : g_a1)  + (size_t)bm0 * PITCH;
    const char* B = (const char*)(MODE ? g_w2t : g_w1t) + (size_t)n0  * PITCH;

    // loader: A 64 rows x 8 chunks = 512 cp16 (4/thread);
    //         B 128 rows x 8 chunks = 1024 cp16 (8/thread)
    const int lrow = tid >> 3, lchk = (tid & 7) * 16;

    auto load_stage = [&](int s) {
        const uint32_t base = sb + (s % 3) * STAGE;
        const size_t kb = (size_t)s * 128;
        #pragma unroll
        for (int i = 0; i < 4; ++i) {
            int r = lrow + i * 16;
            uint32_t so = swz128((uint32_t)(r * 128 + lchk));
            cp16(base + so, A + (size_t)r * PITCH + kb + lchk);
        }
        #pragma unroll
        for (int i = 0; i < 8; ++i) {
            int r = lrow + i * 16;
            uint32_t so = swz128((uint32_t)(r * 128 + lchk));
            cp16(base + B_OFF + so, B + (size_t)r * PITCH + kb + lchk);
        }
    };

    // ldmatrix lane address components
    const int a_row  = lane & 15;                           // + mt*16
    const int a_byte = (lane >> 4) * 16;                    // + ksub*32
    const int b_l8   = lane & 7;
    const int b_grp  = lane >> 3;                           // 0..3
    const int b_row0 = wn * 32 + (b_grp >> 1) * 8 + b_l8;   // + p*16
    const int b_byte = (b_grp & 1) * 16;                    // + ksub*32

    float acc[4][4][4] = {};

    load_stage(0); asm volatile("cp.async.commit_group;" ::: "memory");
    load_stage(1); asm volatile("cp.async.commit_group;" ::: "memory");

    #pragma unroll 1
    for (int c = 0; c < C; ++c) {
        if (c < C - 1) asm volatile("cp.async.wait_group 1;" ::: "memory");
        else           asm volatile("cp.async.wait_group 0;" ::: "memory");
        __syncthreads();

        if (c + 2 < C) {
            load_stage(c + 2);
            asm volatile("cp.async.commit_group;" ::: "memory");
        }

        const uint32_t stb = sb + (c % 3) * STAGE;
        #pragma unroll
        for (int ksub = 0; ksub < 4; ++ksub) {
            uint32_t bf[4][2];
            #pragma unroll
            for (int p = 0; p < 2; ++p) {
                uint32_t r4[4];
                ldsm4(r4, stb + B_OFF +
                    swz128((uint32_t)((b_row0 + p * 16) * 128 + ksub * 32 + b_byte)));
                bf[2 * p][0] = r4[0]; bf[2 * p][1] = r4[1];
                bf[2 * p + 1][0] = r4[2]; bf[2 * p + 1][1] = r4[3];
            }
            #pragma unroll
            for (int mt = 0; mt < 4; ++mt) {
                uint32_t af[4];
                ldsm4(af, stb +
                    swz128((uint32_t)((a_row + mt * 16) * 128 + ksub * 32 + a_byte)));
                #pragma unroll
                for (int nt = 0; nt < 4; ++nt) mma16816(acc[mt][nt], af, bf[nt]);
            }
        }
    }

    // ------------------------- epilogue -------------------------------------
    const int q = lane >> 2;                         // row-in-8
    const int npair = (lane & 3) * 2;

    if constexpr (MODE == 0) {
        #pragma unroll
        for (int nt = 0; nt < 4; ++nt) {
            const int gn = n0 + wn * 32 + nt * 8 + npair;
            const float bv0 = __ldg(bias + gn), bv1 = __ldg(bias + gn + 1);
            #pragma unroll
            for (int mt = 0; mt < 4; ++mt) {
                const int r0 = bm0 + mt * 16 + q;
                __half2 v0 = __floats2half2_rn(fmaxf(acc[mt][nt][0] + bv0, 0.f),
                                               fmaxf(acc[mt][nt][1] + bv1, 0.f));
                __half2 v1 = __floats2half2_rn(fmaxf(acc[mt][nt][2] + bv0, 0.f),
                                               fmaxf(acc[mt][nt][3] + bv1, 0.f));
                *(__half2*)(g_h + (size_t)r0 * HID + gn)       = v0;
                *(__half2*)(g_h + (size_t)(r0 + 8) * HID + gn) = v1;
            }
        }
    } else {
        // Fused coupling: acc pair (c0,c1) = (s_raw, t_raw) for column pair gn.
        float ldp[8] = {0.f, 0.f, 0.f, 0.f, 0.f, 0.f, 0.f, 0.f};
        #pragma unroll
        for (int nt = 0; nt < 4; ++nt) {
            const int gn = n0 + wn * 32 + nt * 8 + npair;
            const float bs = __ldg(bias + gn), bt = __ldg(bias + gn + 1);
            #pragma unroll
            for (int mt = 0; mt < 4; ++mt) {
                const int r0 = bm0 + mt * 16 + q;
                #pragma unroll
                for (int hh = 0; hh < 2; ++hh) {
                    const int r = r0 + hh * 8;
                    float s_raw = acc[mt][nt][2 * hh]     + bs;
                    float t_val = acc[mt][nt][2 * hh + 1] + bt;
                    float e2 = __expf(2.f * s_raw);
                    float s  = 5.f * (1.f - 2.f / (e2 + 1.f));   // 5*tanh
                    ldp[mt * 2 + hh] += s;
                    float2 xv = *(const float2*)(x + (size_t)r * DIM + gn);
                    float2 o  = make_float2(xv.x, xv.y * __expf(s) + t_val);
                    *(float2*)(out + (size_t)r * DIM + gn) = o;
                }
            }
        }
        // quad reduce (lanes of a quad share the same rows)
        #pragma unroll
        for (int i = 0; i < 8; ++i) {
            ldp[i] += __shfl_xor_sync(0xffffffffu, ldp[i], 1);
            ldp[i] += __shfl_xor_sync(0xffffffffu, ldp[i], 2);
        }
        __syncthreads();                     // smem (stages) now reusable
        float* red = (float*)smem;           // [64 rows][4 wn]
        if ((lane & 3) == 0) {
            #pragma unroll
            for (int i = 0; i < 8; ++i) {
                int row_local = (i >> 1) * 16 + q + (i & 1) * 8;
                red[row_local * 4 + wn] = ldp[i];
            }
        }
        __syncthreads();
        if (tid < 64) {
            float p = red[tid * 4] + red[tid * 4 + 1] +
                      red[tid * 4 + 2] + red[tid * 4 + 3];
            g_ldp[blockIdx.x][bm0 + tid] = p;
        }
    }
}

// ------------------------- log_det final reduce -----------------------------
__global__ __launch_bounds__(256)
void ldred(float* __restrict__ out)
{
    int r = blockIdx.x * 256 + threadIdx.x;
    out[(size_t)B_TOT * DIM + r] =
        g_ldp[0][r] + g_ldp[1][r] + g_ldp[2][r] + g_ldp[3][r];
}

// ------------------------- launch ------------------------------------------
extern "C" void kernel_launch(void* const* d_in, const int* in_sizes, int n_in,
                              void* d_out, int out_size)
{
    const float* x   = (const float*)d_in[0];
    const float* ctx = (const float*)d_in[1];
    const float* W1  = (const float*)d_in[2];
    const float* b1  = (const float*)d_in[3];
    const float* W2  = (const float*)d_in[4];
    const float* b2  = (const float*)d_in[5];
    float* out = (float*)d_out;

    cudaFuncSetAttribute(gemm_mma<0>, cudaFuncAttributeMaxDynamicSharedMemorySize, 73728);
    cudaFuncSetAttribute(gemm_mma<1>, cudaFuncAttributeMaxDynamicSharedMemorySize, 73728);

    prep_w1t<<<(HID * KIN + 255) / 256, 256>>>(W1);
    prep_w2t<<<(DIM * HID + 255) / 256, 256>>>(W2, b2);
    prep_a1<<<(int)(((size_t)B_TOT * KIN + 255) / 256), 256>>>(x, ctx);

    gemm_mma<0><<<dim3(HID / 128, B_TOT / 64), 128, 73728>>>(b1, nullptr, nullptr);
    gemm_mma<1><<<dim3(DIM / 128, B_TOT / 64), 128, 73728>>>(nullptr, x, out);

    ldred<<<B_TOT / 256, 256>>>(out);
}